// round 3
// baseline (speedup 1.0000x reference)
#include <cuda_runtime.h>

// ---- problem constants ----
#define LFULL (1 << 20)
#define L1SZ  (1 << 19)
#define L2SZ  (1 << 18)
#define L3SZ  (1 << 17)
#define BATCH 64

// ---- tiling: one block = 512 level-3 outputs of one batch row ----
#define T3   512
#define NCH1 264   // level-1 chunks of 8: p0 = P0-32+8t, t in [0,264)
#define S1P  1056  // float2 pairs: s1p[k] = (lo1[P0-32+2k], lo1[P0-32+2k+1])
#define NCH2 130   // level-2 chunks of 8: ln0 = -8+8c
#define S2P  520   // float2 pairs: s2p[k] = (lo2[N0-8+2k], lo2[N0-8+2k+1])

// ---- flattened output offsets (tuple order: lo3, yh0, yh1, yh2) ----
#define OFF_YH0 8388608L
#define OFF_YH1 41943040L
#define OFF_YH2 75497472L

__global__ __launch_bounds__(256) void dtcwt1d_fused(
    const float* __restrict__ x,
    const float* __restrict__ h0o, const float* __restrict__ h1o,
    const float* __restrict__ h0a,
    float* __restrict__ out)
{
    __shared__ __align__(16) float2 s1p[S1P];
    __shared__ __align__(16) float2 s2p[S2P];

    const int tid = threadIdx.x;
    const int b   = blockIdx.y;
    const int M0  = blockIdx.x * T3;
    const int N0  = 2 * M0;
    const int P0  = 4 * M0;
    const bool edge = (blockIdx.x == 0) || (blockIdx.x == gridDim.x - 1);

    const float* xb = x + (long)b * LFULL;

    // ================= level 1: x (gmem) -> lo1 pairs (smem), hi1 -> gmem ====
    // lo1[p] = sum_t h0o[t] x[2p-2+t], hi1[p] = sum_t h1o[t] x[2p-3+t]
    {
        const float c0=h0o[0],c1=h0o[1],c2=h0o[2],c3=h0o[3],c4=h0o[4];
        const float d0=h1o[0],d1=h1o[1],d2=h1o[2],d3=h1o[3],
                    d4=h1o[4],d5=h1o[5],d6=h1o[6];
        float* yh0 = out + OFF_YH0 + (long)b * L1SZ;
        for (int t = tid; t < NCH1; t += 256) {
            const int  p0 = P0 - 32 + 8 * t;
            const long g0 = 2L * p0 - 4;           // 16B-aligned
            float w[24];
            if (!edge) {
                #pragma unroll
                for (int q = 0; q < 6; ++q) {
                    const float4 v = *(const float4*)(xb + g0 + 4 * q);
                    w[4*q] = v.x; w[4*q+1] = v.y; w[4*q+2] = v.z; w[4*q+3] = v.w;
                }
            } else {
                #pragma unroll
                for (int k = 0; k < 24; ++k) {
                    const long g = g0 + k;
                    w[k] = (g >= 0 && g < LFULL) ? xb[g] : 0.f;
                }
            }
            float lo[8], hi[8];
            #pragma unroll
            for (int j = 0; j < 8; ++j) {
                lo[j] = c0*w[2*j+2] + c1*w[2*j+3] + c2*w[2*j+4]
                      + c3*w[2*j+5] + c4*w[2*j+6];
                hi[j] = d0*w[2*j+1] + d1*w[2*j+2] + d2*w[2*j+3] + d3*w[2*j+4]
                      + d4*w[2*j+5] + d5*w[2*j+6] + d6*w[2*j+7];
            }
            if (edge) {
                #pragma unroll
                for (int j = 0; j < 8; ++j) {
                    const int p = p0 + j;
                    if (p < 0 || p >= L1SZ) lo[j] = 0.f;
                }
            }
            float* sp = (float*)(s1p + 4 * t);
            *(float4*)(sp)     = make_float4(lo[0], lo[1], lo[2], lo[3]);
            *(float4*)(sp + 4) = make_float4(lo[4], lo[5], lo[6], lo[7]);
            if (t >= 4 && t < 260) {   // core: hi1 for p in [P0, P0+2048)
                *(float4*)(yh0 + p0)     = make_float4(hi[0], hi[1], hi[2], hi[3]);
                *(float4*)(yh0 + p0 + 4) = make_float4(hi[4], hi[5], hi[6], hi[7]);
            }
        }
    }
    __syncthreads();

    // ================= level 2: lo1 pairs -> lo2 pairs (smem), hia/hib -> gmem
    // E = sum ae[s]we[s], O = sum ao[s]wo[s]; lo = E+O, hb = O-E,
    // ha = sum ao[6-s]we[s] - sum ae[6-s]wo[s]
    {
        float ae[7], ao[7];
        #pragma unroll
        for (int s = 0; s < 7; ++s) { ae[s] = h0a[2*s]; ao[s] = h0a[2*s+1]; }
        float* yh1 = out + OFF_YH1 + (long)b * (2L * L2SZ);
        for (int c = tid; c < NCH2; c += 256) {
            float E[15], O[15];
            #pragma unroll
            for (int q = 0; q < 8; ++q) {          // s1p[8c+4 .. 8c+19]
                const float4 v = *(const float4*)((const float*)(s1p + 8*c + 4) + 4*q);
                if (2*q < 15)     { E[2*q]   = v.x; O[2*q]   = v.y; }
                if (2*q + 1 < 15) { E[2*q+1] = v.z; O[2*q+1] = v.w; }
            }
            float lo[8], ha[8], hb[8];
            #pragma unroll
            for (int j = 0; j < 8; ++j) {
                float Es = 0.f, Os = 0.f, Pu = 0.f, Qu = 0.f;
                #pragma unroll
                for (int s = 0; s < 7; ++s) {
                    const float ve = E[j+1+s], vo = O[j+1+s];
                    Es += ae[s]   * ve;  Os += ao[s]   * vo;
                    Pu += ao[6-s] * ve;  Qu += ae[6-s] * vo;
                }
                lo[j] = Es + Os;  hb[j] = Os - Es;  ha[j] = Pu - Qu;
            }
            if (edge) {
                #pragma unroll
                for (int j = 0; j < 8; ++j) {
                    const int n = N0 - 8 + 8*c + j;
                    if (n < 0 || n >= L2SZ) lo[j] = 0.f;
                }
            }
            float* sp = (float*)(s2p + 4 * c);
            *(float4*)(sp)     = make_float4(lo[0], lo[1], lo[2], lo[3]);
            *(float4*)(sp + 4) = make_float4(lo[4], lo[5], lo[6], lo[7]);
            if (c >= 1 && c < 129) {   // core: n in [N0, N0+1024)
                const int n0 = N0 + 8 * (c - 1);
                *(float4*)(yh1 + n0)            = make_float4(ha[0],ha[1],ha[2],ha[3]);
                *(float4*)(yh1 + n0 + 4)        = make_float4(ha[4],ha[5],ha[6],ha[7]);
                *(float4*)(yh1 + L2SZ + n0)     = make_float4(hb[0],hb[1],hb[2],hb[3]);
                *(float4*)(yh1 + L2SZ + n0 + 4) = make_float4(hb[4],hb[5],hb[6],hb[7]);
            }
        }
    }
    __syncthreads();

    // ================= level 3: lo2 pairs -> lo3 / hia3 / hib3 (gmem) ========
    if (tid < 128) {
        float ae[7], ao[7];
        #pragma unroll
        for (int s = 0; s < 7; ++s) { ae[s] = h0a[2*s]; ao[s] = h0a[2*s+1]; }
        const int c = tid;                         // chunk of 4: m = M0+4c+j
        float E[11], O[11];
        #pragma unroll
        for (int q = 0; q < 6; ++q) {              // s2p[4c .. 4c+11]
            const float4 v = *(const float4*)((const float*)(s2p + 4*c) + 4*q);
            if (2*q < 11)     { E[2*q]   = v.x; O[2*q]   = v.y; }
            if (2*q + 1 < 11) { E[2*q+1] = v.z; O[2*q+1] = v.w; }
        }
        float lo[4], ha[4], hb[4];
        #pragma unroll
        for (int j = 0; j < 4; ++j) {
            float Es = 0.f, Os = 0.f, Pu = 0.f, Qu = 0.f;
            #pragma unroll
            for (int s = 0; s < 7; ++s) {
                const float ve = E[j+1+s], vo = O[j+1+s];
                Es += ae[s]   * ve;  Os += ao[s]   * vo;
                Pu += ao[6-s] * ve;  Qu += ae[6-s] * vo;
            }
            lo[j] = Es + Os;  hb[j] = Os - Es;  ha[j] = Pu - Qu;
        }
        float* olo = out + (long)b * L3SZ;
        float* yh2 = out + OFF_YH2 + (long)b * (2L * L3SZ);
        const int m = M0 + 4 * c;
        *(float4*)(olo + m)        = make_float4(lo[0], lo[1], lo[2], lo[3]);
        *(float4*)(yh2 + m)        = make_float4(ha[0], ha[1], ha[2], ha[3]);
        *(float4*)(yh2 + L3SZ + m) = make_float4(hb[0], hb[1], hb[2], hb[3]);
    }
}

extern "C" void kernel_launch(void* const* d_in, const int* in_sizes, int n_in,
                              void* d_out, int out_size) {
    (void)in_sizes; (void)n_in; (void)out_size;
    // metadata order: x, h0o, h1o, h0a, h1a, h0b, h1b (qshift filters derived)
    dim3 grid(L3SZ / T3, BATCH);
    dtcwt1d_fused<<<grid, 256>>>(
        (const float*)d_in[0],
        (const float*)d_in[1], (const float*)d_in[2],
        (const float*)d_in[3],
        (float*)d_out);
}